// round 3
// baseline (speedup 1.0000x reference)
#include <cuda_runtime.h>
#include <cuda_bf16.h>
#include <cstdint>

// Problem constants
#define BB   64     // batch
#define NP   900    // predictions (columns)
#define NCLS 128    // classes
#define MT   64     // targets (rows)
#define KC   8      // corners
#define INF_F 1000000000.0f
#define NPK  29     // ceil(900/32) columns per lane

// Transposed cost scratch: CT[b][m][n], contiguous in n for fast row reads in LSA.
__device__ float g_CT[(size_t)BB * MT * NP];

// ---------------------------------------------------------------------------
// Kernel 1: cost matrix. One warp per (b, n). Block = 128 threads = 4 warps.
// Writes C[b][n][m] to d_out and CT[b][m][n] to scratch. (unchanged from R1)
// ---------------------------------------------------------------------------
__global__ void cost_kernel(const float* __restrict__ logits,
                            const float* __restrict__ corners,
                            const int*   __restrict__ labels,
                            const float* __restrict__ boxes,
                            float* __restrict__ outC) {
    int gwarp = (blockIdx.x * blockDim.x + threadIdx.x) >> 5;
    int lane  = threadIdx.x & 31;
    int wloc  = threadIdx.x >> 5;
    if (gwarp >= BB * NP) return;
    int b = gwarp / NP;
    int n = gwarp % NP;

    __shared__ float sh_probs[4][NCLS];
    __shared__ float sh_cen[4][3];

    const float* lg = logits + ((size_t)b * NP + n) * NCLS;
    float l0 = lg[lane], l1 = lg[lane + 32], l2 = lg[lane + 64], l3 = lg[lane + 96];
    float mx = fmaxf(fmaxf(l0, l1), fmaxf(l2, l3));
    #pragma unroll
    for (int o = 16; o; o >>= 1) mx = fmaxf(mx, __shfl_xor_sync(0xffffffffu, mx, o));
    float e0 = expf(l0 - mx), e1 = expf(l1 - mx), e2 = expf(l2 - mx), e3 = expf(l3 - mx);
    float s = e0 + e1 + e2 + e3;
    #pragma unroll
    for (int o = 16; o; o >>= 1) s += __shfl_xor_sync(0xffffffffu, s, o);
    sh_probs[wloc][lane]      = e0 / s;
    sh_probs[wloc][lane + 32] = e1 / s;
    sh_probs[wloc][lane + 64] = e2 / s;
    sh_probs[wloc][lane + 96] = e3 / s;

    const float* cr = corners + ((size_t)b * NP + n) * (KC * 3);
    if (lane < 3) {
        float sum = 0.0f;
        #pragma unroll
        for (int k = 0; k < KC; k++) sum += cr[k * 3 + lane];
        sh_cen[wloc][lane] = sum * 0.125f;
    }
    __syncwarp();

    float cx = sh_cen[wloc][0], cy = sh_cen[wloc][1], cz = sh_cen[wloc][2];

    #pragma unroll
    for (int t = 0; t < 2; t++) {
        int m = lane + t * 32;
        int lab = labels[b * MT + m];
        float cc = -sh_probs[wloc][lab];
        const float* bx = boxes + ((size_t)b * MT + m) * 7;
        float dx = cx - bx[0], dy = cy - bx[1], dz = cz - bx[2];
        float bc = sqrtf(dx * dx + dy * dy + dz * dz);
        float c = cc + 5.0f * bc;
        outC[((size_t)b * NP + n) * MT + m] = c;
        g_CT[((size_t)b * MT + m) * NP + n] = c;
    }
}

// ---------------------------------------------------------------------------
// Order-preserving float <-> u32 encoding for unsigned-min reductions.
// ---------------------------------------------------------------------------
__device__ __forceinline__ unsigned fenc(float f) {
    unsigned u = __float_as_uint(f);
    return u ^ ((u >> 31) ? 0xFFFFFFFFu : 0x80000000u);
}
__device__ __forceinline__ float fdec(unsigned e) {
    unsigned u = (e & 0x80000000u) ? (e ^ 0x80000000u) : ~e;
    return __uint_as_float(u);
}

// ---------------------------------------------------------------------------
// Kernel 2: Jonker-Volgenant LSA, ONE WARP per batch. Bit-exact replication
// of the reference (same op order on minv/u/v, same argmin tie-breaking).
// Lane owns columns j = 1+lane+32k, k=0..28. v, minv in registers; used is a
// register bitmask. p / u_of_col / way in shared. Delta application deferred
// one iteration and fused into the scan (identical float sequence).
// ---------------------------------------------------------------------------
__global__ __launch_bounds__(32, 1)
void lsa_kernel(float* __restrict__ out) {
    const int b    = blockIdx.x;
    const int lane = threadIdx.x;

    __shared__ int   p_sh[NP + 1];
    __shared__ float u_sh[NP + 1];   // u_of_col[j] == u[p_sh[j]]
    __shared__ int   way_sh[NP + 1];

    for (int j = lane; j <= NP; j += 32) { p_sh[j] = 0; u_sh[j] = 0.0f; }
    __syncwarp();

    const float* CT = g_CT + (size_t)b * MT * NP;
    const int jbase = 1 + lane;

    float v[NPK];
    #pragma unroll
    for (int k = 0; k < NPK; k++) v[k] = 0.0f;

    for (int i1 = 1; i1 <= MT; i1++) {
        float minv[NPK];
        #pragma unroll
        for (int k = 0; k < NPK; k++) minv[k] = INF_F;
        unsigned usedm = 0;
        if (lane == 0) { p_sh[0] = i1; u_sh[0] = 0.0f; }
        __syncwarp();

        int   j0   = 0;
        float pend = 0.0f;   // delta from previous iteration, not yet applied

        for (int it = 0; it < MT + 8; it++) {
            int   i0 = p_sh[j0];
            float u0 = u_sh[j0];
            if (i0 == 0) break;  // free column found; flush below

            // mark j0 used (owner lane); old mask used for pending application
            unsigned newm = usedm;
            if (((j0 - 1) & 31) == lane) newm |= 1u << ((j0 - 1) >> 5);

            const float* row = CT + (size_t)(i0 - 1) * NP;

            unsigned bestenc = 0xFFFFFFFFu;
            int      bestj   = 0x7FFFFFFF;
            #pragma unroll
            for (int k = 0; k < NPK; k++) {
                bool valid = (k < NPK - 1) | (lane < 4);
                if (valid) {
                    int j = jbase + 32 * k;
                    // apply pending delta (old mask): used -> v, unused -> minv
                    if ((usedm >> k) & 1) v[k] -= pend;
                    else                  minv[k] -= pend;
                    float cur = row[j - 1] - u0 - v[k];
                    bool isused = (newm >> k) & 1;
                    if (!isused && cur < minv[k]) { minv[k] = cur; way_sh[j] = j0; }
                    float mv = isused ? INF_F : minv[k];
                    unsigned enc = fenc(mv);
                    if (enc < bestenc) { bestenc = enc; bestj = j; }
                }
            }
            // pending delta to u_of_col of previously-used columns (+ column 0)
            unsigned m = usedm;
            while (m) { int k = __ffs(m) - 1; m &= m - 1; u_sh[jbase + 32 * k] += pend; }
            if (lane == 0) u_sh[0] += pend;
            usedm = newm;

            // argmin: value first (order-preserving encoding), then smallest j
            unsigned wenc = __reduce_min_sync(0xffffffffu, bestenc);
            unsigned cand = (bestenc == wenc) ? (unsigned)bestj : 0xFFFFFFFFu;
            j0   = (int)__reduce_min_sync(0xffffffffu, cand);
            pend = fdec(wenc);   // this iteration's delta, applied next iter
        }

        // flush final pending delta to used columns (v and u_of_col)
        #pragma unroll
        for (int k = 0; k < NPK; k++) {
            bool valid = (k < NPK - 1) | (lane < 4);
            if (valid && ((usedm >> k) & 1)) v[k] -= pend;
        }
        {
            unsigned m = usedm;
            while (m) { int k = __ffs(m) - 1; m &= m - 1; u_sh[jbase + 32 * k] += pend; }
            if (lane == 0) u_sh[0] += pend;
        }
        __syncwarp();

        // backtrack augmenting path (serial, lane 0); copy u_of_col with p
        if (lane == 0) {
            int jj = j0;
            for (int s = 0; s < MT + 8 && jj != 0; s++) {
                int jn = way_sh[jj];
                p_sh[jj] = p_sh[jn];
                u_sh[jj] = u_sh[jn];
                jj = jn;
            }
        }
        __syncwarp();
    }

    // outputs: pred_idx (value-cast float), tgt_idx
    float* predf = out + (size_t)BB * NP * MT;
    float* tgtf  = predf + (size_t)BB * MT;
    for (int j = 1 + lane; j <= NP; j += 32) {
        int r = p_sh[j];
        if (r > 0) predf[b * MT + (r - 1)] = (float)(j - 1);
    }
    for (int m = lane; m < MT; m += 32) tgtf[b * MT + m] = (float)m;
}

// ---------------------------------------------------------------------------
extern "C" void kernel_launch(void* const* d_in, const int* in_sizes, int n_in,
                              void* d_out, int out_size) {
    const float* logits  = (const float*)d_in[0];   // [64, 900, 128]
    const float* corners = (const float*)d_in[1];   // [64, 900, 8, 3]
    const int*   labels  = (const int*)  d_in[2];   // [64, 64]
    const float* boxes   = (const float*)d_in[3];   // [64, 64, 7]
    float* out = (float*)d_out;

    (void)in_sizes; (void)n_in; (void)out_size;

    int warps  = BB * NP;
    int blocks = (warps + 3) / 4;
    cost_kernel<<<blocks, 128>>>(logits, corners, labels, boxes, out);

    lsa_kernel<<<BB, 32>>>(out);
}

// round 4
// speedup vs baseline: 1.7643x; 1.7643x over previous
#include <cuda_runtime.h>
#include <cuda_bf16.h>
#include <cstdint>

// Problem constants
#define BB   64     // batch
#define NP   900    // predictions (columns)
#define NCLS 128    // classes
#define MT   64     // targets (rows)
#define KC   8      // corners
#define INF_F 1000000000.0f

#define TLSA 128    // threads per LSA block (4 warps)
#define NPK  8      // ceil(900/128) columns per lane (lanes 0..3 have 8, rest 7)

// Transposed cost scratch: CT[b][m][n], contiguous in n for fast row reads in LSA.
__device__ float g_CT[(size_t)BB * MT * NP];

// ---------------------------------------------------------------------------
// Kernel 1: cost matrix. One warp per (b, n). Block = 128 threads = 4 warps.
// ---------------------------------------------------------------------------
__global__ void cost_kernel(const float* __restrict__ logits,
                            const float* __restrict__ corners,
                            const int*   __restrict__ labels,
                            const float* __restrict__ boxes,
                            float* __restrict__ outC) {
    int gwarp = (blockIdx.x * blockDim.x + threadIdx.x) >> 5;
    int lane  = threadIdx.x & 31;
    int wloc  = threadIdx.x >> 5;
    if (gwarp >= BB * NP) return;
    int b = gwarp / NP;
    int n = gwarp % NP;

    __shared__ float sh_probs[4][NCLS];
    __shared__ float sh_cen[4][3];

    const float* lg = logits + ((size_t)b * NP + n) * NCLS;
    float l0 = lg[lane], l1 = lg[lane + 32], l2 = lg[lane + 64], l3 = lg[lane + 96];
    float mx = fmaxf(fmaxf(l0, l1), fmaxf(l2, l3));
    #pragma unroll
    for (int o = 16; o; o >>= 1) mx = fmaxf(mx, __shfl_xor_sync(0xffffffffu, mx, o));
    float e0 = expf(l0 - mx), e1 = expf(l1 - mx), e2 = expf(l2 - mx), e3 = expf(l3 - mx);
    float s = e0 + e1 + e2 + e3;
    #pragma unroll
    for (int o = 16; o; o >>= 1) s += __shfl_xor_sync(0xffffffffu, s, o);
    sh_probs[wloc][lane]      = e0 / s;
    sh_probs[wloc][lane + 32] = e1 / s;
    sh_probs[wloc][lane + 64] = e2 / s;
    sh_probs[wloc][lane + 96] = e3 / s;

    const float* cr = corners + ((size_t)b * NP + n) * (KC * 3);
    if (lane < 3) {
        float sum = 0.0f;
        #pragma unroll
        for (int k = 0; k < KC; k++) sum += cr[k * 3 + lane];
        sh_cen[wloc][lane] = sum * 0.125f;
    }
    __syncwarp();

    float cx = sh_cen[wloc][0], cy = sh_cen[wloc][1], cz = sh_cen[wloc][2];

    #pragma unroll
    for (int t = 0; t < 2; t++) {
        int m = lane + t * 32;
        int lab = labels[b * MT + m];
        float cc = -sh_probs[wloc][lab];
        const float* bx = boxes + ((size_t)b * MT + m) * 7;
        float dx = cx - bx[0], dy = cy - bx[1], dz = cz - bx[2];
        float bc = sqrtf(dx * dx + dy * dy + dz * dz);
        float c = cc + 5.0f * bc;
        outC[((size_t)b * NP + n) * MT + m] = c;
        g_CT[((size_t)b * MT + m) * NP + n] = c;
    }
}

// ---------------------------------------------------------------------------
// Order-preserving float <-> u32 encoding for unsigned-min reductions.
// ---------------------------------------------------------------------------
__device__ __forceinline__ unsigned fenc(float f) {
    unsigned u = __float_as_uint(f);
    return u ^ (unsigned)(((int)u >> 31) | 0x80000000);
}
__device__ __forceinline__ float fdec(unsigned e) {
    unsigned u = (e & 0x80000000u) ? (e ^ 0x80000000u) : ~e;
    return __uint_as_float(u);
}

// ---------------------------------------------------------------------------
// Kernel 2: Jonker-Volgenant LSA, 4 warps (128 threads) per batch.
// Bit-exact float sequence vs the reference; lane owns columns
// j = 1 + tid + 128k (k=0..7). v, minv in registers; used = 8-bit reg mask.
// Delta application deferred one iteration and fused into the scan.
// Cross-warp argmin via double-buffered smem (one __syncthreads per iter).
// ---------------------------------------------------------------------------
__global__ __launch_bounds__(TLSA, 1)
void lsa_kernel(float* __restrict__ out) {
    const int b    = blockIdx.x;
    const int tid  = threadIdx.x;
    const int lane = tid & 31;
    const int wid  = tid >> 5;

    __shared__ int                p_sh[NP + 1];
    __shared__ float              u_sh[NP + 1];   // u_of_col[j] == u[p_sh[j]]
    __shared__ int                way_sh[NP + 1];
    __shared__ unsigned long long redbuf[2][4];

    for (int j = tid; j <= NP; j += TLSA) { p_sh[j] = 0; u_sh[j] = 0.0f; }
    __syncthreads();

    const float* CT = g_CT + (size_t)b * MT * NP;
    const int jbase = 1 + tid;

    float v[NPK];
    #pragma unroll
    for (int k = 0; k < NPK; k++) v[k] = 0.0f;

    for (int i1 = 1; i1 <= MT; i1++) {
        float minv[NPK];
        #pragma unroll
        for (int k = 0; k < NPK; k++) minv[k] = INF_F;
        unsigned usedm = 0;
        if (tid == 0) { p_sh[0] = i1; u_sh[0] = 0.0f; }
        __syncthreads();

        int   j0   = 0;
        float pend = 0.0f;   // delta from previous iteration, not yet applied

        for (int it = 0; it < MT + 8; it++) {
            int   i0 = p_sh[j0];
            float u0 = u_sh[j0];
            if (i0 == 0) break;  // free column found; flush below

            // mark j0 used (owner lane); old mask drives pending application.
            // j0==0 (dummy col) is excluded: not lane-owned (fixes R2 OOB).
            unsigned newm = usedm;
            if (j0 > 0 && ((j0 - 1) & (TLSA - 1)) == tid)
                newm |= 1u << ((j0 - 1) >> 7);

            const float* rp = CT + (size_t)(i0 - 1) * NP + tid;

            unsigned bestenc = 0xFFFFFFFFu;
            int      bestj   = 0x7FFFFFFF;
            #pragma unroll
            for (int k = 0; k < NPK; k++) {
                bool valid = (k < NPK - 1) | (tid < 4);
                if (valid) {
                    int j = jbase + 128 * k;
                    // apply pending delta (old mask): used -> v, unused -> minv
                    if ((usedm >> k) & 1) v[k] -= pend;
                    else                  minv[k] -= pend;
                    float cur = rp[128 * k] - u0 - v[k];
                    bool isused = (newm >> k) & 1;
                    if (!isused && cur < minv[k]) { minv[k] = cur; way_sh[j] = j0; }
                    float mv = isused ? INF_F : minv[k];
                    unsigned enc = fenc(mv);
                    if (enc < bestenc) { bestenc = enc; bestj = j; }
                }
            }
            // pending delta to u_of_col of previously-used columns (+ col 0)
            unsigned m = usedm;
            while (m) { int k = __ffs(m) - 1; m &= m - 1; u_sh[jbase + 128 * k] += pend; }
            if (tid == 0) u_sh[0] += pend;
            usedm = newm;

            // warp argmin: value first, then smallest j among tied lanes
            unsigned wenc = __reduce_min_sync(0xffffffffu, bestenc);
            unsigned cand = (bestenc == wenc) ? (unsigned)bestj : 0xFFFFFFFFu;
            unsigned wj   = __reduce_min_sync(0xffffffffu, cand);
            if (lane == 0)
                redbuf[it & 1][wid] = ((unsigned long long)wenc << 32) | wj;
            __syncthreads();
            // cross-warp: u64 min gives (min enc, then min j) exactly
            unsigned long long r0 = redbuf[it & 1][0];
            unsigned long long r1 = redbuf[it & 1][1];
            unsigned long long r2 = redbuf[it & 1][2];
            unsigned long long r3 = redbuf[it & 1][3];
            unsigned long long bb = min(min(r0, r1), min(r2, r3));
            j0   = (int)(unsigned)bb;
            pend = fdec((unsigned)(bb >> 32));
        }

        // flush final pending delta to used columns (v and u_of_col)
        #pragma unroll
        for (int k = 0; k < NPK; k++) {
            bool valid = (k < NPK - 1) | (tid < 4);
            if (valid && ((usedm >> k) & 1)) v[k] -= pend;
        }
        {
            unsigned m = usedm;
            while (m) { int k = __ffs(m) - 1; m &= m - 1; u_sh[jbase + 128 * k] += pend; }
            if (tid == 0) u_sh[0] += pend;
        }
        __syncthreads();

        // backtrack augmenting path (serial, tid 0); copy u_of_col with p
        if (tid == 0) {
            int jj = j0;
            for (int s = 0; s < MT + 8 && jj != 0; s++) {
                int jn = way_sh[jj];
                p_sh[jj] = p_sh[jn];
                u_sh[jj] = u_sh[jn];
                jj = jn;
            }
        }
        __syncthreads();
    }

    // outputs: pred_idx (value-cast float), tgt_idx
    float* predf = out + (size_t)BB * NP * MT;
    float* tgtf  = predf + (size_t)BB * MT;
    for (int j = 1 + tid; j <= NP; j += TLSA) {
        int r = p_sh[j];
        if (r > 0) predf[b * MT + (r - 1)] = (float)(j - 1);
    }
    for (int m = tid; m < MT; m += TLSA) tgtf[b * MT + m] = (float)m;
}

// ---------------------------------------------------------------------------
extern "C" void kernel_launch(void* const* d_in, const int* in_sizes, int n_in,
                              void* d_out, int out_size) {
    const float* logits  = (const float*)d_in[0];   // [64, 900, 128]
    const float* corners = (const float*)d_in[1];   // [64, 900, 8, 3]
    const int*   labels  = (const int*)  d_in[2];   // [64, 64]
    const float* boxes   = (const float*)d_in[3];   // [64, 64, 7]
    float* out = (float*)d_out;

    (void)in_sizes; (void)n_in; (void)out_size;

    int warps  = BB * NP;
    int blocks = (warps + 3) / 4;
    cost_kernel<<<blocks, 128>>>(logits, corners, labels, boxes, out);

    lsa_kernel<<<BB, TLSA>>>(out);
}